// round 16
// baseline (speedup 1.0000x reference)
#include <cuda_runtime.h>
#include <cstdint>
#include <math.h>

#define BETA  5.5f
#define NC    1000
#define NM    50
#define ND    1024
#define ND4   256
#define QB    50          // qn partial CTAs (first wave)
#define QROWS 20          // rows per partial CTA (50*20 = 1000)

__device__ __align__(16) float g_qn[ND];
__device__ float g_logits[NC];
__device__ float g_qpart[QB * ND];
__device__ unsigned int g_qtick = 0;
__device__ unsigned int g_qflag = 0;
__device__ unsigned int g_ctr_m = 0;

// ---------------------------------------------------------------------------
// Single kernel: fused qn phase (CTAs 0..49) + per-class attention
// (grid=1000, 1 class/CTA, HW scheduling) + softmax (last-done CTA).
// Mainloop = round-3/13 proven optimum (warp-per-row, register double
// buffer, barrier-free). Class prologue loads (bk/bv + first row) issue
// BEFORE the qn spin so startup DRAM latency hides behind qn compute.
// ---------------------------------------------------------------------------
__global__ void __launch_bounds__(128)
dualmem_kernel(const float* __restrict__ mem,
               const float* __restrict__ van,
               const float* __restrict__ gbk,
               const float* __restrict__ gbv,
               const float* __restrict__ ffn,
               const float* __restrict__ img,
               const float* __restrict__ gb,
               const float* __restrict__ scale,
               float* __restrict__ out)
{
    const int c    = blockIdx.x;        // class id (also phase-0 id if < QB)
    const int t    = threadIdx.x;       // 0..127
    const int wi   = t >> 5;
    const int lane = t & 31;

    __shared__ float4 qn_s[ND4];
    __shared__ float4 bk_s[ND4];
    __shared__ float4 bv_s[ND4];
    __shared__ float4 accs[4][ND4];
    __shared__ float  sw_s[4];
    __shared__ float4 redc[4];
    __shared__ float  red1[4];
    __shared__ float2 red2[4];
    __shared__ float  redm[4], reds[4];
    __shared__ unsigned int utick;

    // ===================== phase 0: qn partials (CTAs 0..QB-1) =============
    if (c < QB) {
        float s[8];
        #pragma unroll
        for (int k = 0; k < 8; ++k) s[k] = 0.0f;
        const float* base = gb + (size_t)c * QROWS * ND;
        for (int r = 0; r < QROWS; ++r) {
            #pragma unroll
            for (int k = 0; k < 8; ++k)
                s[k] += base[(size_t)r * ND + t + k * 128];
        }
        #pragma unroll
        for (int k = 0; k < 8; ++k) g_qpart[c * ND + t + k * 128] = s[k];
        __threadfence();
        __syncthreads();
        if (t == 0) utick = atomicAdd(&g_qtick, 1u);
        __syncthreads();
        if (utick == QB - 1) {
            // finisher: sum partials, add img, l2norm, publish flag
            float q[8];
            float ss = 0.0f;
            #pragma unroll
            for (int k = 0; k < 8; ++k) {
                const int d = t + k * 128;
                float sum = 0.0f;
                #pragma unroll 5
                for (int b = 0; b < QB; ++b) sum += g_qpart[b * ND + d];
                q[k] = img[d] + sum * (1.0f / (float)NC);
                ss += q[k] * q[k];
            }
            #pragma unroll
            for (int o = 16; o; o >>= 1) ss += __shfl_xor_sync(0xffffffffu, ss, o);
            if (lane == 0) red1[wi] = ss;
            __syncthreads();
            const float rq = rsqrtf(red1[0] + red1[1] + red1[2] + red1[3]);
            #pragma unroll
            for (int k = 0; k < 8; ++k) g_qn[t + k * 128] = q[k] * rq;
            __threadfence();
            if (t == 0) atomicExch(&g_qflag, 1u);
        }
    }

    // ===================== class prologue (qn-independent part) ============
    const float4* qn4  = (const float4*)g_qn;
    const float4* gbk4 = (const float4*)(gbk + (size_t)c * ND);
    const float4* gbv4 = (const float4*)(gbv + (size_t)c * ND);
    const float4* mem4 = (const float4*)(mem + (size_t)c * NM * ND);
    const float4* van4 = (const float4*)(van + (size_t)c * ND);

    // stage bk/bv + their norms; load first mem row — all before the spin
    float pqk = 0.0f, pkk = 0.0f, pvv = 0.0f;
    #pragma unroll
    for (int r = 0; r < 2; ++r) {
        const int idx = t + r * 128;
        const float4 k = gbk4[idx];
        const float4 v = gbv4[idx];
        bk_s[idx] = k; bv_s[idx] = v;
        pkk += k.x*k.x + k.y*k.y + k.z*k.z + k.w*k.w;
        pvv += v.x*v.x + v.y*v.y + v.z*v.z + v.w*v.w;
    }
    float4 xr[8], xn[8];
    {
        const float4* rp = (wi < NM) ? (mem4 + (size_t)wi * ND4) : van4;
        #pragma unroll
        for (int j = 0; j < 8; ++j) xr[j] = rp[j * 32 + lane];
    }

    // wait for qn (fast-path: already published for later waves)
    if (t == 0) {
        while (atomicAdd(&g_qflag, 0u) == 0u) __nanosleep(100);
    }
    __syncthreads();

    // stage qn (L1-bypass reads) + qn·bk constant
    #pragma unroll
    for (int r = 0; r < 2; ++r) {
        const int idx = t + r * 128;
        const float4 q = __ldcg(&qn4[idx]);
        const float4 k = bk_s[idx];
        qn_s[idx] = q;
        pqk += q.x*k.x + q.y*k.y + q.z*k.z + q.w*k.w;
    }
    #pragma unroll
    for (int o = 16; o; o >>= 1) {
        pqk += __shfl_xor_sync(0xffffffffu, pqk, o);
        pkk += __shfl_xor_sync(0xffffffffu, pkk, o);
        pvv += __shfl_xor_sync(0xffffffffu, pvv, o);
    }
    if (lane == 0) redc[wi] = make_float4(pqk, pkk, pvv, 0.0f);
    __syncthreads();
    float qk_c = 0.0f, kk_c = 0.0f, vv_c = 0.0f;
    #pragma unroll
    for (int i = 0; i < 4; ++i) {
        qk_c += redc[i].x; kk_c += redc[i].y; vv_c += redc[i].z;
    }

    // ===================== mainloop (round-13 verbatim) =====================
    float4 acc[8];
    #pragma unroll
    for (int j = 0; j < 8; ++j) acc[j] = make_float4(0.f, 0.f, 0.f, 0.f);
    float sw = 0.0f;

    int m = wi;
    while (true) {
        const int  mn = m + 4;
        const bool hn = (mn <= NM);
        if (hn) {
            const float4* rq = (mn < NM) ? (mem4 + (size_t)mn * ND4) : van4;
            #pragma unroll
            for (int j = 0; j < 8; ++j) xn[j] = rq[j * 32 + lane];
        }

        float xx = 0.0f, qx = 0.0f, xk = 0.0f, xv = 0.0f;
        #pragma unroll
        for (int j = 0; j < 8; ++j) {
            const float4 x = xr[j];
            const float4 q = qn_s[j * 32 + lane];
            const float4 k = bk_s[j * 32 + lane];
            const float4 v = bv_s[j * 32 + lane];
            xx += x.x*x.x + x.y*x.y + x.z*x.z + x.w*x.w;
            qx += q.x*x.x + q.y*x.y + q.z*x.z + q.w*x.w;
            xk += k.x*x.x + k.y*x.y + k.z*x.z + k.w*x.w;
            xv += v.x*x.x + v.y*x.y + v.z*x.z + v.w*x.w;
        }
        #pragma unroll
        for (int o = 16; o; o >>= 1) {
            xx += __shfl_xor_sync(0xffffffffu, xx, o);
            qx += __shfl_xor_sync(0xffffffffu, qx, o);
            xk += __shfl_xor_sync(0xffffffffu, xk, o);
            xv += __shfl_xor_sync(0xffffffffu, xv, o);
        }

        float w = 0.0f;
        if (xx != 0.0f) {              // all-zero row <=> |x|^2 == 0
            const float dq = qx + qk_c;
            const float k2 = xx + 2.0f * xk + kk_c;
            const float v2 = xx + 2.0f * xv + vv_c;
            w = __expf(-BETA * (1.0f - dq * rsqrtf(k2))) * rsqrtf(v2);
        }
        sw += w;
        #pragma unroll
        for (int j = 0; j < 8; ++j) {
            acc[j].x += w * xr[j].x;
            acc[j].y += w * xr[j].y;
            acc[j].z += w * xr[j].z;
            acc[j].w += w * xr[j].w;
        }

        if (!hn) break;
        #pragma unroll
        for (int j = 0; j < 8; ++j) xr[j] = xn[j];
        m = mn;
    }

    // --- combine warps: acc_total = sum_w acc + sw_total * bv ---
    #pragma unroll
    for (int j = 0; j < 8; ++j) accs[wi][j * 32 + lane] = acc[j];
    if (lane == 0) sw_s[wi] = sw;
    __syncthreads();

    const float swt = sw_s[0] + sw_s[1] + sw_s[2] + sw_s[3];
    float4 a0, a1;
    {
        const int i0 = t, i1 = t + 128;
        float4 s0 = accs[0][i0], s1 = accs[0][i1];
        #pragma unroll
        for (int w = 1; w < 4; ++w) {
            const float4 p = accs[w][i0], q = accs[w][i1];
            s0.x += p.x; s0.y += p.y; s0.z += p.z; s0.w += p.w;
            s1.x += q.x; s1.y += q.y; s1.z += q.z; s1.w += q.w;
        }
        const float4 b0 = bk_s[0], bb0 = bv_s[i0], bb1 = bv_s[i1];
        (void)b0;
        a0 = make_float4(s0.x + swt*bb0.x, s0.y + swt*bb0.y, s0.z + swt*bb0.z, s0.w + swt*bb0.w);
        a1 = make_float4(s1.x + swt*bb1.x, s1.y + swt*bb1.y, s1.z + swt*bb1.z, s1.w + swt*bb1.w);
    }

    // l2norm(acc)
    float n1 = a0.x*a0.x + a0.y*a0.y + a0.z*a0.z + a0.w*a0.w
             + a1.x*a1.x + a1.y*a1.y + a1.z*a1.z + a1.w*a1.w;
    #pragma unroll
    for (int o = 16; o; o >>= 1) n1 += __shfl_xor_sync(0xffffffffu, n1, o);
    if (lane == 0) red1[wi] = n1;
    __syncthreads();
    const float rin1 = rsqrtf(red1[0] + red1[1] + red1[2] + red1[3]);

    // + ffn, l2norm, dot img
    const float4* ffn4 = (const float4*)(ffn + (size_t)c * ND);
    const float4* img4 = (const float4*)img;
    const float4 f0 = ffn4[t], f1 = ffn4[t + 128];
    const float4 i0 = img4[t], i1 = img4[t + 128];
    const float4 af0 = make_float4(a0.x*rin1 + f0.x, a0.y*rin1 + f0.y,
                                   a0.z*rin1 + f0.z, a0.w*rin1 + f0.w);
    const float4 af1 = make_float4(a1.x*rin1 + f1.x, a1.y*rin1 + f1.y,
                                   a1.z*rin1 + f1.z, a1.w*rin1 + f1.w);

    float n2 = af0.x*af0.x + af0.y*af0.y + af0.z*af0.z + af0.w*af0.w
             + af1.x*af1.x + af1.y*af1.y + af1.z*af1.z + af1.w*af1.w;
    float dp = af0.x*i0.x + af0.y*i0.y + af0.z*i0.z + af0.w*i0.w
             + af1.x*i1.x + af1.y*i1.y + af1.z*i1.z + af1.w*i1.w;
    #pragma unroll
    for (int o = 16; o; o >>= 1) {
        n2 += __shfl_xor_sync(0xffffffffu, n2, o);
        dp += __shfl_xor_sync(0xffffffffu, dp, o);
    }
    if (lane == 0) red2[wi] = make_float2(n2, dp);
    __syncthreads();

    if (t == 0) {
        float n2t = 0.0f, dpt = 0.0f;
        #pragma unroll
        for (int i = 0; i < 4; ++i) { n2t += red2[i].x; dpt += red2[i].y; }
        g_logits[c] = expf(scale[0]) * dpt * rsqrtf(n2t);
    }

    // ===================== last CTA: softmax over g_logits ==================
    __threadfence();
    __syncthreads();
    if (t == 0) utick = atomicAdd(&g_ctr_m, 1u);
    __syncthreads();
    if (utick != NC - 1) return;

    float x[8];
    #pragma unroll
    for (int k = 0; k < 8; ++k) {
        const int i = t + k * 128;
        x[k] = (i < NC) ? g_logits[i] : -INFINITY;
    }
    float mx = x[0];
    #pragma unroll
    for (int k = 1; k < 8; ++k) mx = fmaxf(mx, x[k]);
    #pragma unroll
    for (int o = 16; o; o >>= 1) mx = fmaxf(mx, __shfl_xor_sync(0xffffffffu, mx, o));
    if (lane == 0) redm[wi] = mx;
    __syncthreads();
    mx = fmaxf(fmaxf(redm[0], redm[1]), fmaxf(redm[2], redm[3]));

    float e[8];
    float es = 0.0f;
    #pragma unroll
    for (int k = 0; k < 8; ++k) {
        const int i = t + k * 128;
        e[k] = (i < NC) ? expf(x[k] - mx) : 0.0f;
        es += e[k];
    }
    #pragma unroll
    for (int o = 16; o; o >>= 1) es += __shfl_xor_sync(0xffffffffu, es, o);
    if (lane == 0) reds[wi] = es;
    __syncthreads();
    const float rst = 1.0f / (reds[0] + reds[1] + reds[2] + reds[3]);

    #pragma unroll
    for (int k = 0; k < 8; ++k) {
        const int i = t + k * 128;
        if (i < NC) out[i] = e[k] * rst;
    }
    if (t == 0) {                      // reset for graph replay (race-free:
        g_ctr_m = 0;                   // this CTA is provably last; everyone
        g_qtick = 0;                   // read g_qflag before bumping g_ctr_m)
        g_qflag = 0;
    }
}

// ---------------------------------------------------------------------------
extern "C" void kernel_launch(void* const* d_in, const int* in_sizes, int n_in,
                              void* d_out, int out_size)
{
    const float* img   = (const float*)d_in[0];  // (1, 1024)
    const float* mem   = (const float*)d_in[1];  // (1000, 50, 1024)
    const float* van   = (const float*)d_in[2];  // (1000, 1, 1024)
    const float* gb    = (const float*)d_in[3];  // (1000, 1024)
    const float* gbk   = (const float*)d_in[4];  // (1000, 1024)
    const float* gbv   = (const float*)d_in[5];  // (1000, 1024)
    const float* ffn   = (const float*)d_in[6];  // (1000, 1024)
    const float* scale = (const float*)d_in[7];  // scalar

    dualmem_kernel<<<NC, 128>>>(mem, van, gbk, gbv, ffn, img, gb, scale,
                                (float*)d_out);
}

// round 17
// speedup vs baseline: 1.3780x; 1.3780x over previous
#include <cuda_runtime.h>
#include <cstdint>
#include <math.h>

#define BETA  5.5f
#define NC    1000
#define NM    50
#define ND    1024
#define ND4   256
#define QB    40          // partial-sum blocks for qn
#define QROWS 25          // rows per block (40*25 = 1000)

__device__ __align__(16) float g_qn[ND];
__device__ float g_logits[NC];
__device__ float g_qpart[QB * ND];
__device__ unsigned int g_ctr_q = 0;
__device__ unsigned int g_ctr_m = 0;

// ---------------------------------------------------------------------------
// Kernel 1: qn = l2norm(img + mean(global_bias,0)). grid=40 x 1024, ticketed.
// Balanced two-phase: 40 blocks x 25 rows partials; last block sums 40
// partials (160 KB) and normalizes.
// ---------------------------------------------------------------------------
__global__ void qn_kernel(const float* __restrict__ gb,
                          const float* __restrict__ img)
{
    const int d = threadIdx.x;
    const int b = blockIdx.x;
    const float* base = gb + (size_t)b * QROWS * ND + d;
    float s = 0.0f;
    #pragma unroll 5
    for (int r = 0; r < QROWS; ++r) s += base[r * ND];
    g_qpart[b * ND + d] = s;

    __shared__ unsigned int ticket;
    __threadfence();
    __syncthreads();
    if (d == 0) ticket = atomicAdd(&g_ctr_q, 1u);
    __syncthreads();
    if (ticket != QB - 1) return;

    // last block: finish
    float tsum = 0.0f;
    #pragma unroll 8
    for (int bb = 0; bb < QB; ++bb) tsum += g_qpart[bb * ND + d];
    const float q = img[d] + tsum * (1.0f / (float)NC);

    __shared__ float red[32];
    float v = q * q;
    #pragma unroll
    for (int o = 16; o; o >>= 1) v += __shfl_xor_sync(0xffffffffu, v, o);
    const int w = d >> 5, lane = d & 31;
    if (lane == 0) red[w] = v;
    __syncthreads();
    float tot = 0.0f;
    #pragma unroll
    for (int i = 0; i < 32; ++i) tot += red[i];

    g_qn[d] = q * rsqrtf(tot);
    if (d == 0) g_ctr_q = 0;     // reset for graph replay
}

// ---------------------------------------------------------------------------
// Kernel 2: per-class attention, warp-per-row, barrier-free mainloop.
// grid=1000, block=128 (4 warps). Lane l owns float4 dims {j*32+l : j=0..7}.
// Register double buffer (1 row ahead). Last block runs the softmax.
// (Round-3 configuration: the empirically best main kernel.)
// ---------------------------------------------------------------------------
__global__ void __launch_bounds__(128)
dualmem_main_kernel(const float* __restrict__ mem,
                    const float* __restrict__ van,
                    const float* __restrict__ gbk,
                    const float* __restrict__ gbv,
                    const float* __restrict__ ffn,
                    const float* __restrict__ img,
                    const float* __restrict__ scale,
                    float* __restrict__ out)
{
    const int c    = blockIdx.x;
    const int t    = threadIdx.x;       // 0..127
    const int wi   = t >> 5;
    const int lane = t & 31;

    __shared__ float4 qn_s[ND4];
    __shared__ float4 bk_s[ND4];
    __shared__ float4 bv_s[ND4];
    __shared__ float4 accs[4][ND4];
    __shared__ float  sw_s[4];
    __shared__ float4 redc[4];
    __shared__ float  red1[4];
    __shared__ float2 red2[4];
    __shared__ float  redm[4], reds[4];
    __shared__ unsigned int ticket;

    const float4* qn4  = (const float4*)g_qn;
    const float4* gbk4 = (const float4*)(gbk + (size_t)c * ND);
    const float4* gbv4 = (const float4*)(gbv + (size_t)c * ND);
    const float4* mem4 = (const float4*)(mem + (size_t)c * NM * ND);
    const float4* van4 = (const float4*)(van + (size_t)c * ND);

    // --- prologue: stage qn/bk/bv to smem, per-class constants ---
    float pqk = 0.0f, pkk = 0.0f, pvv = 0.0f;
    #pragma unroll
    for (int r = 0; r < 2; ++r) {
        const int idx = t + r * 128;
        const float4 q = qn4[idx];
        const float4 k = gbk4[idx];
        const float4 v = gbv4[idx];
        qn_s[idx] = q; bk_s[idx] = k; bv_s[idx] = v;
        pqk += q.x*k.x + q.y*k.y + q.z*k.z + q.w*k.w;
        pkk += k.x*k.x + k.y*k.y + k.z*k.z + k.w*k.w;
        pvv += v.x*v.x + v.y*v.y + v.z*v.z + v.w*v.w;
    }
    #pragma unroll
    for (int o = 16; o; o >>= 1) {
        pqk += __shfl_xor_sync(0xffffffffu, pqk, o);
        pkk += __shfl_xor_sync(0xffffffffu, pkk, o);
        pvv += __shfl_xor_sync(0xffffffffu, pvv, o);
    }
    if (lane == 0) redc[wi] = make_float4(pqk, pkk, pvv, 0.0f);
    __syncthreads();
    float qk_c = 0.0f, kk_c = 0.0f, vv_c = 0.0f;
    #pragma unroll
    for (int i = 0; i < 4; ++i) {
        qk_c += redc[i].x; kk_c += redc[i].y; vv_c += redc[i].z;
    }

    // --- mainloop: warp wi handles rows m = wi, wi+4, ..., row NM = vanilla ---
    float4 acc[8];
    #pragma unroll
    for (int j = 0; j < 8; ++j) acc[j] = make_float4(0.f, 0.f, 0.f, 0.f);
    float sw = 0.0f;

    float4 xr[8], xn[8];
    {
        const float4* rp = (wi < NM) ? (mem4 + (size_t)wi * ND4) : van4;
        #pragma unroll
        for (int j = 0; j < 8; ++j) xr[j] = rp[j * 32 + lane];
    }

    int m = wi;
    while (true) {
        const int  mn = m + 4;
        const bool hn = (mn <= NM);
        if (hn) {
            const float4* rq = (mn < NM) ? (mem4 + (size_t)mn * ND4) : van4;
            #pragma unroll
            for (int j = 0; j < 8; ++j) xn[j] = rq[j * 32 + lane];
        }

        float xx = 0.0f, qx = 0.0f, xk = 0.0f, xv = 0.0f;
        #pragma unroll
        for (int j = 0; j < 8; ++j) {
            const float4 x = xr[j];
            const float4 q = qn_s[j * 32 + lane];
            const float4 k = bk_s[j * 32 + lane];
            const float4 v = bv_s[j * 32 + lane];
            xx += x.x*x.x + x.y*x.y + x.z*x.z + x.w*x.w;
            qx += q.x*x.x + q.y*x.y + q.z*x.z + q.w*x.w;
            xk += k.x*x.x + k.y*x.y + k.z*x.z + k.w*x.w;
            xv += v.x*x.x + v.y*x.y + v.z*x.z + v.w*x.w;
        }
        #pragma unroll
        for (int o = 16; o; o >>= 1) {
            xx += __shfl_xor_sync(0xffffffffu, xx, o);
            qx += __shfl_xor_sync(0xffffffffu, qx, o);
            xk += __shfl_xor_sync(0xffffffffu, xk, o);
            xv += __shfl_xor_sync(0xffffffffu, xv, o);
        }

        float w = 0.0f;
        if (xx != 0.0f) {              // all-zero row <=> |x|^2 == 0
            const float dq = qx + qk_c;
            const float k2 = xx + 2.0f * xk + kk_c;
            const float v2 = xx + 2.0f * xv + vv_c;
            w = __expf(-BETA * (1.0f - dq * rsqrtf(k2))) * rsqrtf(v2);
        }
        sw += w;
        #pragma unroll
        for (int j = 0; j < 8; ++j) {
            acc[j].x += w * xr[j].x;
            acc[j].y += w * xr[j].y;
            acc[j].z += w * xr[j].z;
            acc[j].w += w * xr[j].w;
        }

        if (!hn) break;
        #pragma unroll
        for (int j = 0; j < 8; ++j) xr[j] = xn[j];
        m = mn;
    }

    // --- combine warps: acc_total = sum_w acc + sw_total * bv ---
    #pragma unroll
    for (int j = 0; j < 8; ++j) accs[wi][j * 32 + lane] = acc[j];
    if (lane == 0) sw_s[wi] = sw;
    __syncthreads();

    const float swt = sw_s[0] + sw_s[1] + sw_s[2] + sw_s[3];
    float4 a0, a1;
    {
        const int i0 = t, i1 = t + 128;
        float4 s0 = accs[0][i0], s1 = accs[0][i1];
        #pragma unroll
        for (int w = 1; w < 4; ++w) {
            const float4 p = accs[w][i0], q = accs[w][i1];
            s0.x += p.x; s0.y += p.y; s0.z += p.z; s0.w += p.w;
            s1.x += q.x; s1.y += q.y; s1.z += q.z; s1.w += q.w;
        }
        const float4 b0 = bv_s[i0], b1 = bv_s[i1];
        a0 = make_float4(s0.x + swt*b0.x, s0.y + swt*b0.y, s0.z + swt*b0.z, s0.w + swt*b0.w);
        a1 = make_float4(s1.x + swt*b1.x, s1.y + swt*b1.y, s1.z + swt*b1.z, s1.w + swt*b1.w);
    }

    // l2norm(acc)
    float n1 = a0.x*a0.x + a0.y*a0.y + a0.z*a0.z + a0.w*a0.w
             + a1.x*a1.x + a1.y*a1.y + a1.z*a1.z + a1.w*a1.w;
    #pragma unroll
    for (int o = 16; o; o >>= 1) n1 += __shfl_xor_sync(0xffffffffu, n1, o);
    if (lane == 0) red1[wi] = n1;
    __syncthreads();
    const float rin1 = rsqrtf(red1[0] + red1[1] + red1[2] + red1[3]);

    // + ffn, l2norm, dot img
    const float4* ffn4 = (const float4*)(ffn + (size_t)c * ND);
    const float4* img4 = (const float4*)img;
    const float4 f0 = ffn4[t], f1 = ffn4[t + 128];
    const float4 i0 = img4[t], i1 = img4[t + 128];
    const float4 af0 = make_float4(a0.x*rin1 + f0.x, a0.y*rin1 + f0.y,
                                   a0.z*rin1 + f0.z, a0.w*rin1 + f0.w);
    const float4 af1 = make_float4(a1.x*rin1 + f1.x, a1.y*rin1 + f1.y,
                                   a1.z*rin1 + f1.z, a1.w*rin1 + f1.w);

    float n2 = af0.x*af0.x + af0.y*af0.y + af0.z*af0.z + af0.w*af0.w
             + af1.x*af1.x + af1.y*af1.y + af1.z*af1.z + af1.w*af1.w;
    float dp = af0.x*i0.x + af0.y*i0.y + af0.z*i0.z + af0.w*i0.w
             + af1.x*i1.x + af1.y*i1.y + af1.z*i1.z + af1.w*i1.w;
    #pragma unroll
    for (int o = 16; o; o >>= 1) {
        n2 += __shfl_xor_sync(0xffffffffu, n2, o);
        dp += __shfl_xor_sync(0xffffffffu, dp, o);
    }
    if (lane == 0) red2[wi] = make_float2(n2, dp);
    __syncthreads();

    if (t == 0) {
        float n2t = 0.0f, dpt = 0.0f;
        #pragma unroll
        for (int i = 0; i < 4; ++i) { n2t += red2[i].x; dpt += red2[i].y; }
        g_logits[c] = expf(scale[0]) * dpt * rsqrtf(n2t);
    }

    // --- last block: softmax over g_logits into d_out ---
    __threadfence();
    __syncthreads();
    if (t == 0) ticket = atomicAdd(&g_ctr_m, 1u);
    __syncthreads();
    if (ticket != NC - 1) return;

    float x[8];
    #pragma unroll
    for (int k = 0; k < 8; ++k) {
        const int i = t + k * 128;
        x[k] = (i < NC) ? g_logits[i] : -INFINITY;
    }
    float mx = x[0];
    #pragma unroll
    for (int k = 1; k < 8; ++k) mx = fmaxf(mx, x[k]);
    #pragma unroll
    for (int o = 16; o; o >>= 1) mx = fmaxf(mx, __shfl_xor_sync(0xffffffffu, mx, o));
    if (lane == 0) redm[wi] = mx;
    __syncthreads();
    mx = fmaxf(fmaxf(redm[0], redm[1]), fmaxf(redm[2], redm[3]));

    float e[8];
    float es = 0.0f;
    #pragma unroll
    for (int k = 0; k < 8; ++k) {
        const int i = t + k * 128;
        e[k] = (i < NC) ? expf(x[k] - mx) : 0.0f;
        es += e[k];
    }
    #pragma unroll
    for (int o = 16; o; o >>= 1) es += __shfl_xor_sync(0xffffffffu, es, o);
    if (lane == 0) reds[wi] = es;
    __syncthreads();
    const float stot = reds[0] + reds[1] + reds[2] + reds[3];
    const float rst = 1.0f / stot;

    #pragma unroll
    for (int k = 0; k < 8; ++k) {
        const int i = t + k * 128;
        if (i < NC) out[i] = e[k] * rst;
    }
    if (t == 0) g_ctr_m = 0;     // reset for graph replay
}

// ---------------------------------------------------------------------------
extern "C" void kernel_launch(void* const* d_in, const int* in_sizes, int n_in,
                              void* d_out, int out_size)
{
    const float* img   = (const float*)d_in[0];  // (1, 1024)
    const float* mem   = (const float*)d_in[1];  // (1000, 50, 1024)
    const float* van   = (const float*)d_in[2];  // (1000, 1, 1024)
    const float* gb    = (const float*)d_in[3];  // (1000, 1024)
    const float* gbk   = (const float*)d_in[4];  // (1000, 1024)
    const float* gbv   = (const float*)d_in[5];  // (1000, 1024)
    const float* ffn   = (const float*)d_in[6];  // (1000, 1024)
    const float* scale = (const float*)d_in[7];  // scalar

    qn_kernel<<<QB, 1024>>>(gb, img);
    dualmem_main_kernel<<<NC, 128>>>(mem, van, gbk, gbv, ffn, img, scale,
                                     (float*)d_out);
}